// round 6
// baseline (speedup 1.0000x reference)
#include <cuda_runtime.h>
#include <cuda_bf16.h>
#include <math.h>
#include <stdint.h>

#define BSZ   8
#define HD    128
#define LSEQ  8192
#define PD    256
#define NC2   16
#define CL    (LSEQ / NC2)   // 512

// ---------------- scratch ----------------
__device__ __align__(16) float g_br[(size_t)BSZ * PD * LSEQ];   // Bu real (planar b,p,l)
__device__ __align__(16) float g_bi[(size_t)BSZ * PD * LSEQ];   // Bu imag
__device__ __align__(16) __nv_bfloat16 g_xrh[(size_t)BSZ * PD * LSEQ];  // x re hi
__device__ __align__(16) __nv_bfloat16 g_xrl[(size_t)BSZ * PD * LSEQ];  // x re lo
__device__ __align__(16) __nv_bfloat16 g_xih[(size_t)BSZ * PD * LSEQ];  // x im hi
__device__ __align__(16) __nv_bfloat16 g_xil[(size_t)BSZ * PD * LSEQ];  // x im lo
__device__ float2 g_E[BSZ * NC2 * PD];
__device__ float2 g_carry[BSZ * NC2 * PD];
// Packed per-lane mma A-fragments: [m16blk][ks][hi/lo][lane]
__device__ __align__(16) uint4 g_WbPk[32 * 8  * 2 * 32];   // Wb: M=512, K=128
__device__ __align__(16) uint4 g_WcPk[8  * 40 * 2 * 32];   // Wc: M=128, K=640

__device__ __forceinline__ float2 cmul(float2 a, float2 b) {
    return make_float2(a.x * b.x - a.y * b.y, a.x * b.y + a.y * b.x);
}
__device__ __forceinline__ void split2(float v, __nv_bfloat16* hi, __nv_bfloat16* lo) {
    __nv_bfloat16 h = __float2bfloat16(v);
    *hi = h; *lo = __float2bfloat16(v - __bfloat162float(h));
}
__device__ __forceinline__ unsigned pack_split(float w0, float w1, int hl) {
    __nv_bfloat16 h0, l0, h1, l1;
    split2(w0, &h0, &l0); split2(w1, &h1, &l1);
    unsigned a = __bfloat16_as_ushort(hl ? l0 : h0);
    unsigned b = __bfloat16_as_ushort(hl ? l1 : h1);
    return a | (b << 16);
}
__device__ __forceinline__ unsigned pack_hi(float a, float b) {
    return (unsigned)__bfloat16_as_ushort(__float2bfloat16(a)) |
           ((unsigned)__bfloat16_as_ushort(__float2bfloat16(b)) << 16);
}
__device__ __forceinline__ unsigned pack_lo(float a, float b) {
    __nv_bfloat16 h0 = __float2bfloat16(a), h1 = __float2bfloat16(b);
    return (unsigned)__bfloat16_as_ushort(__float2bfloat16(a - __bfloat162float(h0))) |
           ((unsigned)__bfloat16_as_ushort(__float2bfloat16(b - __bfloat162float(h1))) << 16);
}
__device__ __forceinline__ void mma_bf16(float c[4], const unsigned a[4], unsigned b0, unsigned b1) {
    asm volatile(
        "mma.sync.aligned.m16n8k16.row.col.f32.bf16.bf16.f32 "
        "{%0,%1,%2,%3}, {%4,%5,%6,%7}, {%8,%9}, {%0,%1,%2,%3};"
        : "+f"(c[0]), "+f"(c[1]), "+f"(c[2]), "+f"(c[3])
        : "r"(a[0]), "r"(a[1]), "r"(a[2]), "r"(a[3]), "r"(b0), "r"(b1));
}
__device__ __forceinline__ void ldsm_x4_t(unsigned r[4], unsigned addr) {
    asm volatile("ldmatrix.sync.aligned.m8n8.x4.trans.shared.b16 {%0,%1,%2,%3}, [%4];"
                 : "=r"(r[0]), "=r"(r[1]), "=r"(r[2]), "=r"(r[3]) : "r"(addr));
}
__device__ __forceinline__ unsigned smem_u32(const void* p) {
    unsigned a;
    asm("{ .reg .u64 t; cvta.to.shared.u64 t, %1; cvt.u32.u64 %0, t; }" : "=r"(a) : "l"(p));
    return a;
}

// ---------------------------------------------------------------------------
// K0: pack weights into per-lane mma A-fragments (hi/lo split).
// ---------------------------------------------------------------------------
__device__ __forceinline__ float wb_get(int r, int c, const float* Bre, const float* Bim) {
    return (r < 256) ? Bre[r * 128 + c] : Bim[(r - 256) * 128 + c];
}
__device__ __forceinline__ float wc_get(int o, int k, const float* Cre, const float* Cim,
                                        const float* Dm) {
    if (k < 256) return Cre[o * 256 + k];
    if (k < 512) return -Cim[o * 256 + (k - 256)];
    return Dm[o * 128 + (k - 512)];
}
__global__ void __launch_bounds__(256) k0_prep(
    const float* __restrict__ Bre, const float* __restrict__ Bim,
    const float* __restrict__ Cre, const float* __restrict__ Cim,
    const float* __restrict__ Dm)
{
    int idx = blockIdx.x * 256 + threadIdx.x;
    if (idx < 32 * 8 * 2 * 32) {
        int lane = idx & 31, hl = (idx >> 5) & 1, ks = (idx >> 6) & 7, blk = idx >> 9;
        int r = blk * 16 + (lane >> 2);
        int cb = ks * 16 + (lane & 3) * 2;
        uint4 o;
        o.x = pack_split(wb_get(r,     cb,     Bre, Bim), wb_get(r,     cb + 1, Bre, Bim), hl);
        o.y = pack_split(wb_get(r + 8, cb,     Bre, Bim), wb_get(r + 8, cb + 1, Bre, Bim), hl);
        o.z = pack_split(wb_get(r,     cb + 8, Bre, Bim), wb_get(r,     cb + 9, Bre, Bim), hl);
        o.w = pack_split(wb_get(r + 8, cb + 8, Bre, Bim), wb_get(r + 8, cb + 9, Bre, Bim), hl);
        g_WbPk[idx] = o;
    }
    if (idx < 8 * 40 * 2 * 32) {
        int lane = idx & 31, hl = (idx >> 5) & 1, t = idx >> 6;
        int ks = t % 40, blk = t / 40;
        int r = blk * 16 + (lane >> 2);
        int cb = ks * 16 + (lane & 3) * 2;
        uint4 o;
        o.x = pack_split(wc_get(r,     cb,     Cre, Cim, Dm), wc_get(r,     cb + 1, Cre, Cim, Dm), hl);
        o.y = pack_split(wc_get(r + 8, cb,     Cre, Cim, Dm), wc_get(r + 8, cb + 1, Cre, Cim, Dm), hl);
        o.z = pack_split(wc_get(r,     cb + 8, Cre, Cim, Dm), wc_get(r,     cb + 9, Cre, Cim, Dm), hl);
        o.w = pack_split(wc_get(r + 8, cb + 8, Cre, Cim, Dm), wc_get(r + 8, cb + 9, Cre, Cim, Dm), hl);
        g_WcPk[idx] = o;
    }
}

// ---------------------------------------------------------------------------
// mma over staged [NKS*16 k][128 l] tile (SROW padded rows).
// ---------------------------------------------------------------------------
#define SROW 136

template<int NKS>
__device__ __forceinline__ void mma_block(float c[2][8][4], const uint4* wpk, int ks_stride,
                                          int blk0, int blk1, int ksg0,
                                          unsigned sh_base, unsigned sl_base,
                                          int lane, int wn)
{
    const int brow = (lane & 7) + (lane & 8);
    const int bcol = ((lane >> 4) << 3);
#pragma unroll
    for (int ks = 0; ks < NKS; ks++) {
        const int km = ks * 16;
        const int ksg = ksg0 + ks;
        uint4 ah0 = wpk[((blk0 * ks_stride + ksg) * 2 + 0) * 32 + lane];
        uint4 al0 = wpk[((blk0 * ks_stride + ksg) * 2 + 1) * 32 + lane];
        uint4 ah1 = wpk[((blk1 * ks_stride + ksg) * 2 + 0) * 32 + lane];
        uint4 al1 = wpk[((blk1 * ks_stride + ksg) * 2 + 1) * 32 + lane];
#pragma unroll
        for (int ng = 0; ng < 4; ng++) {
            int n0 = wn * 64 + ng * 16;
            unsigned off = (unsigned)(((km + brow) * SROW + n0 + bcol) * 2);
            unsigned bh[4], bl[4];
            ldsm_x4_t(bh, sh_base + off);
            ldsm_x4_t(bl, sl_base + off);
            mma_bf16(c[0][ng * 2 + 0], (const unsigned*)&ah0, bh[0], bh[1]);
            mma_bf16(c[0][ng * 2 + 0], (const unsigned*)&ah0, bl[0], bl[1]);
            mma_bf16(c[0][ng * 2 + 0], (const unsigned*)&al0, bh[0], bh[1]);
            mma_bf16(c[0][ng * 2 + 1], (const unsigned*)&ah0, bh[2], bh[3]);
            mma_bf16(c[0][ng * 2 + 1], (const unsigned*)&ah0, bl[2], bl[3]);
            mma_bf16(c[0][ng * 2 + 1], (const unsigned*)&al0, bh[2], bh[3]);
            mma_bf16(c[1][ng * 2 + 0], (const unsigned*)&ah1, bh[0], bh[1]);
            mma_bf16(c[1][ng * 2 + 0], (const unsigned*)&ah1, bl[0], bl[1]);
            mma_bf16(c[1][ng * 2 + 0], (const unsigned*)&al1, bh[0], bh[1]);
            mma_bf16(c[1][ng * 2 + 1], (const unsigned*)&ah1, bh[2], bh[3]);
            mma_bf16(c[1][ng * 2 + 1], (const unsigned*)&ah1, bl[2], bl[3]);
            mma_bf16(c[1][ng * 2 + 1], (const unsigned*)&al1, bh[2], bh[3]);
        }
    }
}

// ---------------------------------------------------------------------------
// K1: [Bre;Bim](512x128) @ u(128 x L) -> planar g_br/g_bi.
// One CTA stages FULL K=128 u-tile once, loops 4 m-tiles. grid (L/128, 1, BSZ).
// Dynamic smem: sh[128][SROW] + sl[128][SROW] bf16 = 69632 B.
// ---------------------------------------------------------------------------
__global__ void __launch_bounds__(256) k1_bu(const float* __restrict__ u)
{
    extern __shared__ __align__(16) __nv_bfloat16 dsm[];
    __nv_bfloat16 (*sh)[SROW] = (__nv_bfloat16(*)[SROW])dsm;
    __nv_bfloat16 (*sl)[SROW] = (__nv_bfloat16(*)[SROW])(dsm + 128 * SROW);

    const int b = blockIdx.z, lbase = blockIdx.x * 128;
    const int tid = threadIdx.x, lane = tid & 31, wid = tid >> 5;
    const int wm = wid >> 1, wn = wid & 1;
    const unsigned sh_base = smem_u32(&sh[0][0]);
    const unsigned sl_base = smem_u32(&sl[0][0]);

    // stage full 128k x 128l fp32 -> split bf16
    {
        const int row = tid >> 1, half = tid & 1;
        const float* s = u + ((size_t)b * HD + row) * LSEQ + lbase + half * 64;
#pragma unroll
        for (int q = 0; q < 8; q++) {
            float4 v0 = *(const float4*)(s + q * 8);
            float4 v1 = *(const float4*)(s + q * 8 + 4);
            uint4 hi, lo;
            hi.x = pack_hi(v0.x, v0.y); lo.x = pack_lo(v0.x, v0.y);
            hi.y = pack_hi(v0.z, v0.w); lo.y = pack_lo(v0.z, v0.w);
            hi.z = pack_hi(v1.x, v1.y); lo.z = pack_lo(v1.x, v1.y);
            hi.w = pack_hi(v1.z, v1.w); lo.w = pack_lo(v1.z, v1.w);
            *(uint4*)&sh[row][half * 64 + q * 8] = hi;
            *(uint4*)&sl[row][half * 64 + q * 8] = lo;
        }
    }
    __syncthreads();

#pragma unroll 1
    for (int mt = 0; mt < 4; mt++) {
        float c[2][8][4];
#pragma unroll
        for (int mi = 0; mi < 2; mi++)
#pragma unroll
            for (int ni = 0; ni < 8; ni++)
#pragma unroll
                for (int q = 0; q < 4; q++) c[mi][ni][q] = 0.f;

        const int blk0 = mt * 8 + wm * 2;
        mma_block<8>(c, g_WbPk, 8, blk0, blk0 + 1, 0, sh_base, sl_base, lane, wn);

#pragma unroll
        for (int mi = 0; mi < 2; mi++) {
#pragma unroll
            for (int ni = 0; ni < 8; ni++) {
                int r0  = mt * 128 + wm * 32 + mi * 16 + (lane >> 2);
                int col = lbase + wn * 64 + ni * 8 + (lane & 3) * 2;
                {
                    float* plane = (r0 < 256) ? g_br : g_bi;
                    int pr = (r0 < 256) ? r0 : r0 - 256;
                    *(float2*)&plane[((size_t)b * PD + pr) * LSEQ + col] =
                        make_float2(c[mi][ni][0], c[mi][ni][1]);
                }
                int r1 = r0 + 8;
                {
                    float* plane = (r1 < 256) ? g_br : g_bi;
                    int pr = (r1 < 256) ? r1 : r1 - 256;
                    *(float2*)&plane[((size_t)b * PD + pr) * LSEQ + col] =
                        make_float2(c[mi][ni][2], c[mi][ni][3]);
                }
            }
        }
    }
}

// ---------------------------------------------------------------------------
// K2 warp-scan; k2c writes x as bf16 hi/lo planes.
// ---------------------------------------------------------------------------
__device__ __forceinline__ void lane_powers(float2 a, int lane, float2* ap, float2* w1m)
{
    float invn = 1.f / (a.x * a.x + a.y * a.y);
    float2 ainv = make_float2(a.x * invn, -a.y * invn);
    float2 pp = make_float2(1.f, 0.f), pn = make_float2(1.f, 0.f);
    float2 t = a, ti = ainv;
#pragma unroll
    for (int bit = 1; bit < 32; bit <<= 1) {
        if (lane & bit) { pp = cmul(pp, t); pn = cmul(pn, ti); }
        t = cmul(t, t); ti = cmul(ti, ti);
    }
    *ap = pp; *w1m = cmul(a, pn);
}

template <bool WRITE_X, bool LOAD_CARRY>
__device__ __forceinline__ void scan_chunk(const float* Are, const float* Aim)
{
    const int b = blockIdx.z, c = blockIdx.x;
    const int wid = threadIdx.x >> 5, lane = threadIdx.x & 31;
    const int p = blockIdx.y * 8 + wid;
    const float2 a = make_float2(Are[p], Aim[p]);
    float2 ap, w1m;
    lane_powers(a, lane, &ap, &w1m);

    const size_t base = ((size_t)b * PD + p) * LSEQ + (size_t)c * CL;
    float2 carry = make_float2(0.f, 0.f);
    if (LOAD_CARRY) carry = g_carry[(b * NC2 + c) * PD + p];

#pragma unroll 4
    for (int s = 0; s < CL / 32; s++) {
        size_t idx = base + s * 32 + lane;
        float br = g_br[idx], bi = g_bi[idx];
        float2 w = make_float2(br * w1m.x - bi * w1m.y, br * w1m.y + bi * w1m.x);
#pragma unroll
        for (int d = 1; d < 32; d <<= 1) {
            float ox = __shfl_up_sync(0xffffffffu, w.x, d);
            float oy = __shfl_up_sync(0xffffffffu, w.y, d);
            if (lane >= d) { w.x += ox; w.y += oy; }
        }
        float2 ac = cmul(a, carry);
        float2 x  = cmul(ap, make_float2(ac.x + w.x, ac.y + w.y));
        if (WRITE_X) {
            __nv_bfloat16 h, l;
            split2(x.x, &h, &l); g_xrh[idx] = h; g_xrl[idx] = l;
            split2(x.y, &h, &l); g_xih[idx] = h; g_xil[idx] = l;
        }
        carry.x = __shfl_sync(0xffffffffu, x.x, 31);
        carry.y = __shfl_sync(0xffffffffu, x.y, 31);
    }
    if (!WRITE_X && lane == 0)
        g_E[(b * NC2 + c) * PD + p] = carry;
}

__global__ void __launch_bounds__(256) k2a_local(
    const float* __restrict__ Are, const float* __restrict__ Aim)
{ scan_chunk<false, false>(Are, Aim); }

__global__ void __launch_bounds__(256) k2c_replay(
    const float* __restrict__ Are, const float* __restrict__ Aim)
{ scan_chunk<true, true>(Are, Aim); }

__global__ void __launch_bounds__(256) k2b_carry(
    const float* __restrict__ Are, const float* __restrict__ Aim)
{
    const int b = blockIdx.x, p = threadIdx.x;
    float2 a = make_float2(Are[p], Aim[p]);
    float2 aT = a;
#pragma unroll
    for (int k = 0; k < 9; k++) aT = cmul(aT, aT);   // a^512
    float2 E[NC2];
#pragma unroll
    for (int c = 0; c < NC2; c++) E[c] = g_E[(b * NC2 + c) * PD + p];
    float2 S = make_float2(0.f, 0.f);
#pragma unroll
    for (int c = 0; c < NC2; c++) {
        g_carry[(b * NC2 + c) * PD + p] = S;
        S = make_float2(aT.x * S.x - aT.y * S.y + E[c].x,
                        aT.x * S.y + aT.y * S.x + E[c].y);
    }
}

// ---------------------------------------------------------------------------
// K3: [Cre|-Cim|D](128x640) @ [x_re;x_im;u](640 x L) + GELU. grid (L/128, BSZ).
// Chunks 0-7: pure bf16 copy staging from x planes. Chunks 8-9: fp32 u split.
// ---------------------------------------------------------------------------
__global__ void __launch_bounds__(256) k3_out(const float* __restrict__ u,
                                              float* __restrict__ out)
{
    __shared__ __align__(16) __nv_bfloat16 sh[64][SROW];
    __shared__ __align__(16) __nv_bfloat16 sl[64][SROW];

    const int b = blockIdx.y, lbase = blockIdx.x * 128;
    const int tid = threadIdx.x, lane = tid & 31, wid = tid >> 5;
    const int wm = wid >> 1, wn = wid & 1;
    const unsigned sh_base = smem_u32(&sh[0][0]);
    const unsigned sl_base = smem_u32(&sl[0][0]);

    float c[2][8][4];
#pragma unroll
    for (int mi = 0; mi < 2; mi++)
#pragma unroll
        for (int ni = 0; ni < 8; ni++)
#pragma unroll
            for (int q = 0; q < 4; q++) c[mi][ni][q] = 0.f;

    uint4 pv[8];

    auto prefetch = [&](int cc) {
        if (cc < 8) {
            const int comp = cc >> 2;
            const __nv_bfloat16* hiA = comp ? g_xih : g_xrh;
            const __nv_bfloat16* loA = comp ? g_xil : g_xrl;
            const __nv_bfloat16* src = (tid >= 128) ? loA : hiA;
            const int row = (tid >> 1) & 63, half = tid & 1;
            const uint4* s = (const uint4*)(src +
                ((size_t)b * PD + (cc & 3) * 64 + row) * LSEQ + lbase + half * 64);
#pragma unroll
            for (int q = 0; q < 8; q++) pv[q] = s[q];
        } else {
            const int row = tid >> 2, quarter = tid & 3;
            const uint4* s = (const uint4*)(u +
                ((size_t)b * HD + (cc - 8) * 64 + row) * LSEQ + lbase + quarter * 32);
#pragma unroll
            for (int q = 0; q < 8; q++) pv[q] = s[q];
        }
    };
    auto stage = [&](int cc) {
        if (cc < 8) {
            const int row = (tid >> 1) & 63, half = tid & 1;
            __nv_bfloat16 (*dst)[SROW] = (tid >= 128) ? sl : sh;
#pragma unroll
            for (int q = 0; q < 8; q++)
                *(uint4*)&dst[row][half * 64 + q * 8] = pv[q];
        } else {
            const int row = tid >> 2, quarter = tid & 3;
#pragma unroll
            for (int q = 0; q < 4; q++) {
                float4 v0 = *(float4*)&pv[2 * q];
                float4 v1 = *(float4*)&pv[2 * q + 1];
                uint4 hi, lo;
                hi.x = pack_hi(v0.x, v0.y); lo.x = pack_lo(v0.x, v0.y);
                hi.y = pack_hi(v0.z, v0.w); lo.y = pack_lo(v0.z, v0.w);
                hi.z = pack_hi(v1.x, v1.y); lo.z = pack_lo(v1.x, v1.y);
                hi.w = pack_hi(v1.z, v1.w); lo.w = pack_lo(v1.z, v1.w);
                *(uint4*)&sh[row][quarter * 32 + q * 8] = hi;
                *(uint4*)&sl[row][quarter * 32 + q * 8] = lo;
            }
        }
    };

    prefetch(0);
    const int blk0 = wm * 2;
#pragma unroll 1
    for (int cc = 0; cc < 10; cc++) {
        stage(cc);
        __syncthreads();
        if (cc < 9) prefetch(cc + 1);
        mma_block<4>(c, g_WcPk, 40, blk0, blk0 + 1, cc * 4, sh_base, sl_base, lane, wn);
        __syncthreads();
    }

#pragma unroll
    for (int mi = 0; mi < 2; mi++) {
#pragma unroll
        for (int ni = 0; ni < 8; ni++) {
            int r0  = wm * 32 + mi * 16 + (lane >> 2);
            int col = lbase + wn * 64 + ni * 8 + (lane & 3) * 2;
            float y0 = c[mi][ni][0], y1 = c[mi][ni][1];
            float y2 = c[mi][ni][2], y3 = c[mi][ni][3];
            y0 = 0.5f * y0 * (1.f + erff(y0 * 0.70710678118654752f));
            y1 = 0.5f * y1 * (1.f + erff(y1 * 0.70710678118654752f));
            y2 = 0.5f * y2 * (1.f + erff(y2 * 0.70710678118654752f));
            y3 = 0.5f * y3 * (1.f + erff(y3 * 0.70710678118654752f));
            *(float2*)&out[((size_t)b * HD + r0) * LSEQ + col]     = make_float2(y0, y1);
            *(float2*)&out[((size_t)b * HD + r0 + 8) * LSEQ + col] = make_float2(y2, y3);
        }
    }
}

// ---------------------------------------------------------------------------
extern "C" void kernel_launch(void* const* d_in, const int* in_sizes, int n_in,
                              void* d_out, int out_size)
{
    (void)in_sizes; (void)n_in; (void)out_size;
    const float* u   = (const float*)d_in[0];
    const float* Are = (const float*)d_in[1];
    const float* Aim = (const float*)d_in[2];
    const float* Bre = (const float*)d_in[3];
    const float* Bim = (const float*)d_in[4];
    const float* Cre = (const float*)d_in[5];
    const float* Cim = (const float*)d_in[6];
    const float* Dm  = (const float*)d_in[7];
    float* out = (float*)d_out;

    const int K1_DYN = 2 * 128 * SROW * (int)sizeof(__nv_bfloat16);  // 69632
    cudaFuncSetAttribute(k1_bu, cudaFuncAttributeMaxDynamicSharedMemorySize, K1_DYN);

    k0_prep    <<<80, 256>>>(Bre, Bim, Cre, Cim, Dm);
    k1_bu      <<<dim3(LSEQ / 128, 1, BSZ), 256, K1_DYN>>>(u);
    k2a_local  <<<dim3(NC2, PD / 8, BSZ), 256>>>(Are, Aim);
    k2b_carry  <<<BSZ, 256>>>(Are, Aim);
    k2c_replay <<<dim3(NC2, PD / 8, BSZ), 256>>>(Are, Aim);
    k3_out     <<<dim3(LSEQ / 128, BSZ), 256>>>(u, out);
}

// round 7
// speedup vs baseline: 1.2828x; 1.2828x over previous
#include <cuda_runtime.h>
#include <cuda_fp16.h>
#include <math.h>
#include <stdint.h>

#define BSZ   8
#define HD    128
#define LSEQ  8192
#define PD    256
#define NC2   16
#define CL    (LSEQ / NC2)   // 512

// ---------------- scratch ----------------
__device__ __align__(16) float g_br[(size_t)BSZ * PD * LSEQ];   // Bu real (planar b,p,l) fp32
__device__ __align__(16) float g_bi[(size_t)BSZ * PD * LSEQ];   // Bu imag
__device__ __align__(16) __half g_xr[(size_t)BSZ * PD * LSEQ];  // x real (fp16)
__device__ __align__(16) __half g_xi[(size_t)BSZ * PD * LSEQ];  // x imag (fp16)
__device__ float2 g_E[BSZ * NC2 * PD];
__device__ float2 g_carry[BSZ * NC2 * PD];
// Packed per-lane mma A-fragments (fp16 hi/lo): [m16blk][ks][hi/lo][lane]
__device__ __align__(16) uint4 g_WbPk[32 * 8  * 2 * 32];   // Wb: M=512, K=128
__device__ __align__(16) uint4 g_WcPk[8  * 40 * 2 * 32];   // Wc: M=128, K=640

__device__ __forceinline__ float2 cmul(float2 a, float2 b) {
    return make_float2(a.x * b.x - a.y * b.y, a.x * b.y + a.y * b.x);
}
__device__ __forceinline__ unsigned pack_f16(float a, float b) {
    __half2 h = __floats2half2_rn(a, b);
    return *(unsigned*)&h;
}
__device__ __forceinline__ unsigned pack_split_f16(float w0, float w1, int hl) {
    __half h0 = __float2half_rn(w0), h1 = __float2half_rn(w1);
    if (!hl) {
        __half2 h = __halves2half2(h0, h1);
        return *(unsigned*)&h;
    }
    __half l0 = __float2half_rn(w0 - __half2float(h0));
    __half l1 = __float2half_rn(w1 - __half2float(h1));
    __half2 l = __halves2half2(l0, l1);
    return *(unsigned*)&l;
}
__device__ __forceinline__ void mma_f16(float c[4], const unsigned a[4], unsigned b0, unsigned b1) {
    asm volatile(
        "mma.sync.aligned.m16n8k16.row.col.f32.f16.f16.f32 "
        "{%0,%1,%2,%3}, {%4,%5,%6,%7}, {%8,%9}, {%0,%1,%2,%3};"
        : "+f"(c[0]), "+f"(c[1]), "+f"(c[2]), "+f"(c[3])
        : "r"(a[0]), "r"(a[1]), "r"(a[2]), "r"(a[3]), "r"(b0), "r"(b1));
}
__device__ __forceinline__ void ldsm_x4_t(unsigned r[4], unsigned addr) {
    asm volatile("ldmatrix.sync.aligned.m8n8.x4.trans.shared.b16 {%0,%1,%2,%3}, [%4];"
                 : "=r"(r[0]), "=r"(r[1]), "=r"(r[2]), "=r"(r[3]) : "r"(addr));
}
__device__ __forceinline__ unsigned smem_u32(const void* p) {
    unsigned a;
    asm("{ .reg .u64 t; cvta.to.shared.u64 t, %1; cvt.u32.u64 %0, t; }" : "=r"(a) : "l"(p));
    return a;
}

// ---------------------------------------------------------------------------
// K0: pack weights into per-lane mma A-fragments (fp16 hi/lo split).
// ---------------------------------------------------------------------------
__device__ __forceinline__ float wb_get(int r, int c, const float* Bre, const float* Bim) {
    return (r < 256) ? Bre[r * 128 + c] : Bim[(r - 256) * 128 + c];
}
__device__ __forceinline__ float wc_get(int o, int k, const float* Cre, const float* Cim,
                                        const float* Dm) {
    if (k < 256) return Cre[o * 256 + k];
    if (k < 512) return -Cim[o * 256 + (k - 256)];
    return Dm[o * 128 + (k - 512)];
}
__global__ void __launch_bounds__(256) k0_prep(
    const float* __restrict__ Bre, const float* __restrict__ Bim,
    const float* __restrict__ Cre, const float* __restrict__ Cim,
    const float* __restrict__ Dm)
{
    int idx = blockIdx.x * 256 + threadIdx.x;
    if (idx < 32 * 8 * 2 * 32) {
        int lane = idx & 31, hl = (idx >> 5) & 1, ks = (idx >> 6) & 7, blk = idx >> 9;
        int r = blk * 16 + (lane >> 2);
        int cb = ks * 16 + (lane & 3) * 2;
        uint4 o;
        o.x = pack_split_f16(wb_get(r,     cb,     Bre, Bim), wb_get(r,     cb + 1, Bre, Bim), hl);
        o.y = pack_split_f16(wb_get(r + 8, cb,     Bre, Bim), wb_get(r + 8, cb + 1, Bre, Bim), hl);
        o.z = pack_split_f16(wb_get(r,     cb + 8, Bre, Bim), wb_get(r,     cb + 9, Bre, Bim), hl);
        o.w = pack_split_f16(wb_get(r + 8, cb + 8, Bre, Bim), wb_get(r + 8, cb + 9, Bre, Bim), hl);
        g_WbPk[idx] = o;
    }
    if (idx < 8 * 40 * 2 * 32) {
        int lane = idx & 31, hl = (idx >> 5) & 1, t = idx >> 6;
        int ks = t % 40, blk = t / 40;
        int r = blk * 16 + (lane >> 2);
        int cb = ks * 16 + (lane & 3) * 2;
        uint4 o;
        o.x = pack_split_f16(wc_get(r,     cb,     Cre, Cim, Dm), wc_get(r,     cb + 1, Cre, Cim, Dm), hl);
        o.y = pack_split_f16(wc_get(r + 8, cb,     Cre, Cim, Dm), wc_get(r + 8, cb + 1, Cre, Cim, Dm), hl);
        o.z = pack_split_f16(wc_get(r,     cb + 8, Cre, Cim, Dm), wc_get(r,     cb + 9, Cre, Cim, Dm), hl);
        o.w = pack_split_f16(wc_get(r + 8, cb + 8, Cre, Cim, Dm), wc_get(r + 8, cb + 9, Cre, Cim, Dm), hl);
        g_WcPk[idx] = o;
    }
}

// ---------------------------------------------------------------------------
// mma over staged [NKS*16 k][128 l] fp16 tile (SROW padded rows).
// 2 mma per accumulator: W_hi*data + W_lo*data.
// ---------------------------------------------------------------------------
#define SROW 136

template<int NKS>
__device__ __forceinline__ void mma_block(float c[2][8][4], const uint4* wpk, int ks_stride,
                                          int blk0, int blk1, int ksg0,
                                          unsigned s_base, int lane, int wn)
{
    const int brow = (lane & 7) + (lane & 8);
    const int bcol = ((lane >> 4) << 3);
#pragma unroll
    for (int ks = 0; ks < NKS; ks++) {
        const int km = ks * 16;
        const int ksg = ksg0 + ks;
        uint4 ah0 = wpk[((blk0 * ks_stride + ksg) * 2 + 0) * 32 + lane];
        uint4 al0 = wpk[((blk0 * ks_stride + ksg) * 2 + 1) * 32 + lane];
        uint4 ah1 = wpk[((blk1 * ks_stride + ksg) * 2 + 0) * 32 + lane];
        uint4 al1 = wpk[((blk1 * ks_stride + ksg) * 2 + 1) * 32 + lane];
#pragma unroll
        for (int ng = 0; ng < 4; ng++) {
            int n0 = wn * 64 + ng * 16;
            unsigned off = (unsigned)(((km + brow) * SROW + n0 + bcol) * 2);
            unsigned bb[4];
            ldsm_x4_t(bb, s_base + off);
            mma_f16(c[0][ng * 2 + 0], (const unsigned*)&ah0, bb[0], bb[1]);
            mma_f16(c[0][ng * 2 + 0], (const unsigned*)&al0, bb[0], bb[1]);
            mma_f16(c[0][ng * 2 + 1], (const unsigned*)&ah0, bb[2], bb[3]);
            mma_f16(c[0][ng * 2 + 1], (const unsigned*)&al0, bb[2], bb[3]);
            mma_f16(c[1][ng * 2 + 0], (const unsigned*)&ah1, bb[0], bb[1]);
            mma_f16(c[1][ng * 2 + 0], (const unsigned*)&al1, bb[0], bb[1]);
            mma_f16(c[1][ng * 2 + 1], (const unsigned*)&ah1, bb[2], bb[3]);
            mma_f16(c[1][ng * 2 + 1], (const unsigned*)&al1, bb[2], bb[3]);
        }
    }
}

// ---------------------------------------------------------------------------
// K1: [Bre;Bim](512x128) @ u(128 x L) -> planar g_br/g_bi fp32.
// One CTA stages FULL K=128 fp16 u-tile (34.8 KB static), loops 4 m-tiles.
// grid (L/128, 1, BSZ)
// ---------------------------------------------------------------------------
__global__ void __launch_bounds__(256) k1_bu(const float* __restrict__ u)
{
    __shared__ __align__(16) __half sh[128][SROW];

    const int b = blockIdx.z, lbase = blockIdx.x * 128;
    const int tid = threadIdx.x, lane = tid & 31, wid = tid >> 5;
    const int wm = wid >> 1, wn = wid & 1;
    const unsigned s_base = smem_u32(&sh[0][0]);

    // stage full 128k x 128l fp32 -> fp16
    {
        const int row = tid >> 1, half = tid & 1;
        const float* s = u + ((size_t)b * HD + row) * LSEQ + lbase + half * 64;
#pragma unroll
        for (int q = 0; q < 8; q++) {
            float4 v0 = *(const float4*)(s + q * 8);
            float4 v1 = *(const float4*)(s + q * 8 + 4);
            uint4 pk;
            pk.x = pack_f16(v0.x, v0.y); pk.y = pack_f16(v0.z, v0.w);
            pk.z = pack_f16(v1.x, v1.y); pk.w = pack_f16(v1.z, v1.w);
            *(uint4*)&sh[row][half * 64 + q * 8] = pk;
        }
    }
    __syncthreads();

#pragma unroll 1
    for (int mt = 0; mt < 4; mt++) {
        float c[2][8][4];
#pragma unroll
        for (int mi = 0; mi < 2; mi++)
#pragma unroll
            for (int ni = 0; ni < 8; ni++)
#pragma unroll
                for (int q = 0; q < 4; q++) c[mi][ni][q] = 0.f;

        const int blk0 = mt * 8 + wm * 2;
        mma_block<8>(c, g_WbPk, 8, blk0, blk0 + 1, 0, s_base, lane, wn);

#pragma unroll
        for (int mi = 0; mi < 2; mi++) {
#pragma unroll
            for (int ni = 0; ni < 8; ni++) {
                int r0  = mt * 128 + wm * 32 + mi * 16 + (lane >> 2);
                int col = lbase + wn * 64 + ni * 8 + (lane & 3) * 2;
                {
                    float* plane = (r0 < 256) ? g_br : g_bi;
                    int pr = (r0 < 256) ? r0 : r0 - 256;
                    *(float2*)&plane[((size_t)b * PD + pr) * LSEQ + col] =
                        make_float2(c[mi][ni][0], c[mi][ni][1]);
                }
                int r1 = r0 + 8;
                {
                    float* plane = (r1 < 256) ? g_br : g_bi;
                    int pr = (r1 < 256) ? r1 : r1 - 256;
                    *(float2*)&plane[((size_t)b * PD + pr) * LSEQ + col] =
                        make_float2(c[mi][ni][2], c[mi][ni][3]);
                }
            }
        }
    }
}

// ---------------------------------------------------------------------------
// K2 warp-scan; k2c writes x as fp16 planes.
// ---------------------------------------------------------------------------
__device__ __forceinline__ void lane_powers(float2 a, int lane, float2* ap, float2* w1m)
{
    float invn = 1.f / (a.x * a.x + a.y * a.y);
    float2 ainv = make_float2(a.x * invn, -a.y * invn);
    float2 pp = make_float2(1.f, 0.f), pn = make_float2(1.f, 0.f);
    float2 t = a, ti = ainv;
#pragma unroll
    for (int bit = 1; bit < 32; bit <<= 1) {
        if (lane & bit) { pp = cmul(pp, t); pn = cmul(pn, ti); }
        t = cmul(t, t); ti = cmul(ti, ti);
    }
    *ap = pp; *w1m = cmul(a, pn);
}

template <bool WRITE_X, bool LOAD_CARRY>
__device__ __forceinline__ void scan_chunk(const float* Are, const float* Aim)
{
    const int b = blockIdx.z, c = blockIdx.x;
    const int wid = threadIdx.x >> 5, lane = threadIdx.x & 31;
    const int p = blockIdx.y * 8 + wid;
    const float2 a = make_float2(Are[p], Aim[p]);
    float2 ap, w1m;
    lane_powers(a, lane, &ap, &w1m);

    const size_t base = ((size_t)b * PD + p) * LSEQ + (size_t)c * CL;
    float2 carry = make_float2(0.f, 0.f);
    if (LOAD_CARRY) carry = g_carry[(b * NC2 + c) * PD + p];

#pragma unroll 4
    for (int s = 0; s < CL / 32; s++) {
        size_t idx = base + s * 32 + lane;
        float br = g_br[idx], bi = g_bi[idx];
        float2 w = make_float2(br * w1m.x - bi * w1m.y, br * w1m.y + bi * w1m.x);
#pragma unroll
        for (int d = 1; d < 32; d <<= 1) {
            float ox = __shfl_up_sync(0xffffffffu, w.x, d);
            float oy = __shfl_up_sync(0xffffffffu, w.y, d);
            if (lane >= d) { w.x += ox; w.y += oy; }
        }
        float2 ac = cmul(a, carry);
        float2 x  = cmul(ap, make_float2(ac.x + w.x, ac.y + w.y));
        if (WRITE_X) {
            g_xr[idx] = __float2half_rn(x.x);
            g_xi[idx] = __float2half_rn(x.y);
        }
        carry.x = __shfl_sync(0xffffffffu, x.x, 31);
        carry.y = __shfl_sync(0xffffffffu, x.y, 31);
    }
    if (!WRITE_X && lane == 0)
        g_E[(b * NC2 + c) * PD + p] = carry;
}

__global__ void __launch_bounds__(256) k2a_local(
    const float* __restrict__ Are, const float* __restrict__ Aim)
{ scan_chunk<false, false>(Are, Aim); }

__global__ void __launch_bounds__(256) k2c_replay(
    const float* __restrict__ Are, const float* __restrict__ Aim)
{ scan_chunk<true, true>(Are, Aim); }

__global__ void __launch_bounds__(256) k2b_carry(
    const float* __restrict__ Are, const float* __restrict__ Aim)
{
    const int b = blockIdx.x, p = threadIdx.x;
    float2 a = make_float2(Are[p], Aim[p]);
    float2 aT = a;
#pragma unroll
    for (int k = 0; k < 9; k++) aT = cmul(aT, aT);   // a^512
    float2 E[NC2];
#pragma unroll
    for (int c = 0; c < NC2; c++) E[c] = g_E[(b * NC2 + c) * PD + p];
    float2 S = make_float2(0.f, 0.f);
#pragma unroll
    for (int c = 0; c < NC2; c++) {
        g_carry[(b * NC2 + c) * PD + p] = S;
        S = make_float2(aT.x * S.x - aT.y * S.y + E[c].x,
                        aT.x * S.y + aT.y * S.x + E[c].y);
    }
}

// ---------------------------------------------------------------------------
// K3: [Cre|-Cim|D](128x640) @ [x_re;x_im;u](640 x L) + GELU. grid (L/128, BSZ).
// Chunks 0-7: pure fp16 copy staging from x planes. Chunks 8-9: fp32 u -> fp16.
// ---------------------------------------------------------------------------
__global__ void __launch_bounds__(256) k3_out(const float* __restrict__ u,
                                              float* __restrict__ out)
{
    __shared__ __align__(16) __half sh[64][SROW];

    const int b = blockIdx.y, lbase = blockIdx.x * 128;
    const int tid = threadIdx.x, lane = tid & 31, wid = tid >> 5;
    const int wm = wid >> 1, wn = wid & 1;
    const unsigned s_base = smem_u32(&sh[0][0]);
    const int row = tid >> 2, quarter = tid & 3;

    float c[2][8][4];
#pragma unroll
    for (int mi = 0; mi < 2; mi++)
#pragma unroll
        for (int ni = 0; ni < 8; ni++)
#pragma unroll
            for (int q = 0; q < 4; q++) c[mi][ni][q] = 0.f;

    uint4 pv[8];

    auto prefetch = [&](int cc) {
        if (cc < 8) {
            const __half* src = (cc >= 4) ? g_xi : g_xr;
            const uint4* s = (const uint4*)(src +
                ((size_t)b * PD + (cc & 3) * 64 + row) * LSEQ + lbase + quarter * 32);
#pragma unroll
            for (int q = 0; q < 4; q++) pv[q] = s[q];
        } else {
            const uint4* s = (const uint4*)(u +
                ((size_t)b * HD + (cc - 8) * 64 + row) * LSEQ + lbase + quarter * 32);
#pragma unroll
            for (int q = 0; q < 8; q++) pv[q] = s[q];
        }
    };
    auto stage = [&](int cc) {
        if (cc < 8) {
#pragma unroll
            for (int q = 0; q < 4; q++)
                *(uint4*)&sh[row][quarter * 32 + q * 8] = pv[q];
        } else {
#pragma unroll
            for (int q = 0; q < 4; q++) {
                float4 v0 = *(float4*)&pv[2 * q];
                float4 v1 = *(float4*)&pv[2 * q + 1];
                uint4 pk;
                pk.x = pack_f16(v0.x, v0.y); pk.y = pack_f16(v0.z, v0.w);
                pk.z = pack_f16(v1.x, v1.y); pk.w = pack_f16(v1.z, v1.w);
                *(uint4*)&sh[row][quarter * 32 + q * 8] = pk;
            }
        }
    };

    prefetch(0);
    const int blk0 = wm * 2;
#pragma unroll 1
    for (int cc = 0; cc < 10; cc++) {
        stage(cc);
        __syncthreads();
        if (cc < 9) prefetch(cc + 1);
        mma_block<4>(c, g_WcPk, 40, blk0, blk0 + 1, cc * 4, s_base, lane, wn);
        __syncthreads();
    }

#pragma unroll
    for (int mi = 0; mi < 2; mi++) {
#pragma unroll
        for (int ni = 0; ni < 8; ni++) {
            int r0  = wm * 32 + mi * 16 + (lane >> 2);
            int col = lbase + wn * 64 + ni * 8 + (lane & 3) * 2;
            float y0 = c[mi][ni][0], y1 = c[mi][ni][1];
            float y2 = c[mi][ni][2], y3 = c[mi][ni][3];
            y0 = 0.5f * y0 * (1.f + erff(y0 * 0.70710678118654752f));
            y1 = 0.5f * y1 * (1.f + erff(y1 * 0.70710678118654752f));
            y2 = 0.5f * y2 * (1.f + erff(y2 * 0.70710678118654752f));
            y3 = 0.5f * y3 * (1.f + erff(y3 * 0.70710678118654752f));
            *(float2*)&out[((size_t)b * HD + r0) * LSEQ + col]     = make_float2(y0, y1);
            *(float2*)&out[((size_t)b * HD + r0 + 8) * LSEQ + col] = make_float2(y2, y3);
        }
    }
}

// ---------------------------------------------------------------------------
extern "C" void kernel_launch(void* const* d_in, const int* in_sizes, int n_in,
                              void* d_out, int out_size)
{
    (void)in_sizes; (void)n_in; (void)out_size;
    const float* u   = (const float*)d_in[0];
    const float* Are = (const float*)d_in[1];
    const float* Aim = (const float*)d_in[2];
    const float* Bre = (const float*)d_in[3];
    const float* Bim = (const float*)d_in[4];
    const float* Cre = (const float*)d_in[5];
    const float* Cim = (const float*)d_in[6];
    const float* Dm  = (const float*)d_in[7];
    float* out = (float*)d_out;

    k0_prep    <<<80, 256>>>(Bre, Bim, Cre, Cim, Dm);
    k1_bu      <<<dim3(LSEQ / 128, 1, BSZ), 256>>>(u);
    k2a_local  <<<dim3(NC2, PD / 8, BSZ), 256>>>(Are, Aim);
    k2b_carry  <<<BSZ, 256>>>(Are, Aim);
    k2c_replay <<<dim3(NC2, PD / 8, BSZ), 256>>>(Are, Aim);
    k3_out     <<<dim3(LSEQ / 128, BSZ), 256>>>(u, out);
}

// round 8
// speedup vs baseline: 1.4850x; 1.1576x over previous
#include <cuda_runtime.h>
#include <cuda_fp16.h>
#include <math.h>
#include <stdint.h>

#define BSZ   8
#define HD    128
#define LSEQ  8192
#define PD    256
#define NC2   16
#define CL    (LSEQ / NC2)   // 512

// ---------------- scratch ----------------
__device__ __align__(16) __half g_brh[(size_t)BSZ * PD * LSEQ];  // Bu real (planar b,p,l) fp16
__device__ __align__(16) __half g_bih[(size_t)BSZ * PD * LSEQ];  // Bu imag
__device__ __align__(16) __half g_xr[(size_t)BSZ * PD * LSEQ];   // x real (fp16)
__device__ __align__(16) __half g_xi[(size_t)BSZ * PD * LSEQ];   // x imag (fp16)
__device__ float2 g_E[BSZ * NC2 * PD];
__device__ float2 g_carry[BSZ * NC2 * PD];
// Packed per-lane mma A-fragments (fp16): Wb hi only, Wc hi/lo
__device__ __align__(16) uint4 g_WbPk[32 * 8 * 32];        // [m16blk][ks][lane]
__device__ __align__(16) uint4 g_WcPk[8 * 40 * 2 * 32];    // [m16blk][ks][hi/lo][lane]

__device__ __forceinline__ float2 cmul(float2 a, float2 b) {
    return make_float2(a.x * b.x - a.y * b.y, a.x * b.y + a.y * b.x);
}
__device__ __forceinline__ unsigned pack_f16(float a, float b) {
    __half2 h = __floats2half2_rn(a, b);
    return *(unsigned*)&h;
}
__device__ __forceinline__ unsigned pack_split_f16(float w0, float w1, int hl) {
    __half h0 = __float2half_rn(w0), h1 = __float2half_rn(w1);
    if (!hl) {
        __half2 h = __halves2half2(h0, h1);
        return *(unsigned*)&h;
    }
    __half l0 = __float2half_rn(w0 - __half2float(h0));
    __half l1 = __float2half_rn(w1 - __half2float(h1));
    __half2 l = __halves2half2(l0, l1);
    return *(unsigned*)&l;
}
__device__ __forceinline__ void mma_f16(float c[4], const unsigned a[4], unsigned b0, unsigned b1) {
    asm volatile(
        "mma.sync.aligned.m16n8k16.row.col.f32.f16.f16.f32 "
        "{%0,%1,%2,%3}, {%4,%5,%6,%7}, {%8,%9}, {%0,%1,%2,%3};"
        : "+f"(c[0]), "+f"(c[1]), "+f"(c[2]), "+f"(c[3])
        : "r"(a[0]), "r"(a[1]), "r"(a[2]), "r"(a[3]), "r"(b0), "r"(b1));
}
__device__ __forceinline__ void ldsm_x4_t(unsigned r[4], unsigned addr) {
    asm volatile("ldmatrix.sync.aligned.m8n8.x4.trans.shared.b16 {%0,%1,%2,%3}, [%4];"
                 : "=r"(r[0]), "=r"(r[1]), "=r"(r[2]), "=r"(r[3]) : "r"(addr));
}
__device__ __forceinline__ unsigned smem_u32(const void* p) {
    unsigned a;
    asm("{ .reg .u64 t; cvta.to.shared.u64 t, %1; cvt.u32.u64 %0, t; }" : "=r"(a) : "l"(p));
    return a;
}

// ---------------------------------------------------------------------------
// K0: pack weights. Wb: hi only. Wc: hi/lo split.
// ---------------------------------------------------------------------------
__device__ __forceinline__ float wb_get(int r, int c, const float* Bre, const float* Bim) {
    return (r < 256) ? Bre[r * 128 + c] : Bim[(r - 256) * 128 + c];
}
__device__ __forceinline__ float wc_get(int o, int k, const float* Cre, const float* Cim,
                                        const float* Dm) {
    if (k < 256) return Cre[o * 256 + k];
    if (k < 512) return -Cim[o * 256 + (k - 256)];
    return Dm[o * 128 + (k - 512)];
}
__global__ void __launch_bounds__(256) k0_prep(
    const float* __restrict__ Bre, const float* __restrict__ Bim,
    const float* __restrict__ Cre, const float* __restrict__ Cim,
    const float* __restrict__ Dm)
{
    int idx = blockIdx.x * 256 + threadIdx.x;
    if (idx < 32 * 8 * 32) {
        int lane = idx & 31, ks = (idx >> 5) & 7, blk = idx >> 8;
        int r = blk * 16 + (lane >> 2);
        int cb = ks * 16 + (lane & 3) * 2;
        uint4 o;
        o.x = pack_f16(wb_get(r,     cb,     Bre, Bim), wb_get(r,     cb + 1, Bre, Bim));
        o.y = pack_f16(wb_get(r + 8, cb,     Bre, Bim), wb_get(r + 8, cb + 1, Bre, Bim));
        o.z = pack_f16(wb_get(r,     cb + 8, Bre, Bim), wb_get(r,     cb + 9, Bre, Bim));
        o.w = pack_f16(wb_get(r + 8, cb + 8, Bre, Bim), wb_get(r + 8, cb + 9, Bre, Bim));
        g_WbPk[idx] = o;
    }
    if (idx < 8 * 40 * 2 * 32) {
        int lane = idx & 31, hl = (idx >> 5) & 1, t = idx >> 6;
        int ks = t % 40, blk = t / 40;
        int r = blk * 16 + (lane >> 2);
        int cb = ks * 16 + (lane & 3) * 2;
        uint4 o;
        o.x = pack_split_f16(wc_get(r,     cb,     Cre, Cim, Dm), wc_get(r,     cb + 1, Cre, Cim, Dm), hl);
        o.y = pack_split_f16(wc_get(r + 8, cb,     Cre, Cim, Dm), wc_get(r + 8, cb + 1, Cre, Cim, Dm), hl);
        o.z = pack_split_f16(wc_get(r,     cb + 8, Cre, Cim, Dm), wc_get(r,     cb + 9, Cre, Cim, Dm), hl);
        o.w = pack_split_f16(wc_get(r + 8, cb + 8, Cre, Cim, Dm), wc_get(r + 8, cb + 9, Cre, Cim, Dm), hl);
        g_WcPk[idx] = o;
    }
}

// ---------------------------------------------------------------------------
// mma over staged [NKS*16 k][128 l] fp16 tile.
// SPLIT: 2 mma per acc (W_hi + W_lo). !SPLIT: 1 mma per acc.
// ---------------------------------------------------------------------------
#define SROW 136

template<int NKS, bool SPLIT>
__device__ __forceinline__ void mma_block(float c[2][8][4], const uint4* wpk, int ks_stride,
                                          int blk0, int blk1, int ksg0,
                                          unsigned s_base, int lane, int wn)
{
    const int brow = (lane & 7) + (lane & 8);
    const int bcol = ((lane >> 4) << 3);
#pragma unroll
    for (int ks = 0; ks < NKS; ks++) {
        const int km = ks * 16;
        const int ksg = ksg0 + ks;
        uint4 ah0, al0, ah1, al1;
        if (SPLIT) {
            ah0 = wpk[((blk0 * ks_stride + ksg) * 2 + 0) * 32 + lane];
            al0 = wpk[((blk0 * ks_stride + ksg) * 2 + 1) * 32 + lane];
            ah1 = wpk[((blk1 * ks_stride + ksg) * 2 + 0) * 32 + lane];
            al1 = wpk[((blk1 * ks_stride + ksg) * 2 + 1) * 32 + lane];
        } else {
            ah0 = wpk[(blk0 * ks_stride + ksg) * 32 + lane];
            ah1 = wpk[(blk1 * ks_stride + ksg) * 32 + lane];
        }
#pragma unroll
        for (int ng = 0; ng < 4; ng++) {
            int n0 = wn * 64 + ng * 16;
            unsigned off = (unsigned)(((km + brow) * SROW + n0 + bcol) * 2);
            unsigned bb[4];
            ldsm_x4_t(bb, s_base + off);
            mma_f16(c[0][ng * 2 + 0], (const unsigned*)&ah0, bb[0], bb[1]);
            mma_f16(c[0][ng * 2 + 1], (const unsigned*)&ah0, bb[2], bb[3]);
            mma_f16(c[1][ng * 2 + 0], (const unsigned*)&ah1, bb[0], bb[1]);
            mma_f16(c[1][ng * 2 + 1], (const unsigned*)&ah1, bb[2], bb[3]);
            if (SPLIT) {
                mma_f16(c[0][ng * 2 + 0], (const unsigned*)&al0, bb[0], bb[1]);
                mma_f16(c[0][ng * 2 + 1], (const unsigned*)&al0, bb[2], bb[3]);
                mma_f16(c[1][ng * 2 + 0], (const unsigned*)&al1, bb[0], bb[1]);
                mma_f16(c[1][ng * 2 + 1], (const unsigned*)&al1, bb[2], bb[3]);
            }
        }
    }
}

// ---------------------------------------------------------------------------
// K1: [Bre;Bim](512x128) @ u(128 x L) -> fp16 planar g_brh/g_bih.
// One CTA stages FULL K=128 fp16 u-tile, loops 4 m-tiles. grid (L/128, 1, BSZ)
// ---------------------------------------------------------------------------
__global__ void __launch_bounds__(256) k1_bu(const float* __restrict__ u)
{
    __shared__ __align__(16) __half sh[128][SROW];

    const int b = blockIdx.z, lbase = blockIdx.x * 128;
    const int tid = threadIdx.x, lane = tid & 31, wid = tid >> 5;
    const int wm = wid >> 1, wn = wid & 1;
    const unsigned s_base = smem_u32(&sh[0][0]);

    // stage full 128k x 128l fp32 -> fp16
    {
        const int row = tid >> 1, half = tid & 1;
        const float* s = u + ((size_t)b * HD + row) * LSEQ + lbase + half * 64;
#pragma unroll
        for (int q = 0; q < 8; q++) {
            float4 v0 = *(const float4*)(s + q * 8);
            float4 v1 = *(const float4*)(s + q * 8 + 4);
            uint4 pk;
            pk.x = pack_f16(v0.x, v0.y); pk.y = pack_f16(v0.z, v0.w);
            pk.z = pack_f16(v1.x, v1.y); pk.w = pack_f16(v1.z, v1.w);
            *(uint4*)&sh[row][half * 64 + q * 8] = pk;
        }
    }
    __syncthreads();

#pragma unroll 1
    for (int mt = 0; mt < 4; mt++) {
        float c[2][8][4];
#pragma unroll
        for (int mi = 0; mi < 2; mi++)
#pragma unroll
            for (int ni = 0; ni < 8; ni++)
#pragma unroll
                for (int q = 0; q < 4; q++) c[mi][ni][q] = 0.f;

        const int blk0 = mt * 8 + wm * 2;
        mma_block<8, false>(c, g_WbPk, 8, blk0, blk0 + 1, 0, s_base, lane, wn);

#pragma unroll
        for (int mi = 0; mi < 2; mi++) {
#pragma unroll
            for (int ni = 0; ni < 8; ni++) {
                int r0  = mt * 128 + wm * 32 + mi * 16 + (lane >> 2);
                int col = lbase + wn * 64 + ni * 8 + (lane & 3) * 2;
                {
                    __half* plane = (r0 < 256) ? g_brh : g_bih;
                    int pr = (r0 < 256) ? r0 : r0 - 256;
                    __half2 h = __floats2half2_rn(c[mi][ni][0], c[mi][ni][1]);
                    *(__half2*)&plane[((size_t)b * PD + pr) * LSEQ + col] = h;
                }
                int r1 = r0 + 8;
                {
                    __half* plane = (r1 < 256) ? g_brh : g_bih;
                    int pr = (r1 < 256) ? r1 : r1 - 256;
                    __half2 h = __floats2half2_rn(c[mi][ni][2], c[mi][ni][3]);
                    *(__half2*)&plane[((size_t)b * PD + pr) * LSEQ + col] = h;
                }
            }
        }
    }
}

// ---------------------------------------------------------------------------
// K2 warp-scan over fp16 Bu; fp32 arithmetic; k2c writes x fp16 planes.
// ---------------------------------------------------------------------------
__device__ __forceinline__ void lane_powers(float2 a, int lane, float2* ap, float2* w1m)
{
    float invn = 1.f / (a.x * a.x + a.y * a.y);
    float2 ainv = make_float2(a.x * invn, -a.y * invn);
    float2 pp = make_float2(1.f, 0.f), pn = make_float2(1.f, 0.f);
    float2 t = a, ti = ainv;
#pragma unroll
    for (int bit = 1; bit < 32; bit <<= 1) {
        if (lane & bit) { pp = cmul(pp, t); pn = cmul(pn, ti); }
        t = cmul(t, t); ti = cmul(ti, ti);
    }
    *ap = pp; *w1m = cmul(a, pn);
}

template <bool WRITE_X, bool LOAD_CARRY>
__device__ __forceinline__ void scan_chunk(const float* Are, const float* Aim)
{
    const int b = blockIdx.z, c = blockIdx.x;
    const int wid = threadIdx.x >> 5, lane = threadIdx.x & 31;
    const int p = blockIdx.y * 8 + wid;
    const float2 a = make_float2(Are[p], Aim[p]);
    float2 ap, w1m;
    lane_powers(a, lane, &ap, &w1m);

    const size_t base = ((size_t)b * PD + p) * LSEQ + (size_t)c * CL;
    float2 carry = make_float2(0.f, 0.f);
    if (LOAD_CARRY) carry = g_carry[(b * NC2 + c) * PD + p];

#pragma unroll 4
    for (int s = 0; s < CL / 32; s++) {
        size_t idx = base + s * 32 + lane;
        float br = __half2float(g_brh[idx]);
        float bi = __half2float(g_bih[idx]);
        float2 w = make_float2(br * w1m.x - bi * w1m.y, br * w1m.y + bi * w1m.x);
#pragma unroll
        for (int d = 1; d < 32; d <<= 1) {
            float ox = __shfl_up_sync(0xffffffffu, w.x, d);
            float oy = __shfl_up_sync(0xffffffffu, w.y, d);
            if (lane >= d) { w.x += ox; w.y += oy; }
        }
        float2 ac = cmul(a, carry);
        float2 x  = cmul(ap, make_float2(ac.x + w.x, ac.y + w.y));
        if (WRITE_X) {
            g_xr[idx] = __float2half_rn(x.x);
            g_xi[idx] = __float2half_rn(x.y);
        }
        carry.x = __shfl_sync(0xffffffffu, x.x, 31);
        carry.y = __shfl_sync(0xffffffffu, x.y, 31);
    }
    if (!WRITE_X && lane == 0)
        g_E[(b * NC2 + c) * PD + p] = carry;
}

__global__ void __launch_bounds__(256) k2a_local(
    const float* __restrict__ Are, const float* __restrict__ Aim)
{ scan_chunk<false, false>(Are, Aim); }

__global__ void __launch_bounds__(256) k2c_replay(
    const float* __restrict__ Are, const float* __restrict__ Aim)
{ scan_chunk<true, true>(Are, Aim); }

__global__ void __launch_bounds__(256) k2b_carry(
    const float* __restrict__ Are, const float* __restrict__ Aim)
{
    const int b = blockIdx.x, p = threadIdx.x;
    float2 a = make_float2(Are[p], Aim[p]);
    float2 aT = a;
#pragma unroll
    for (int k = 0; k < 9; k++) aT = cmul(aT, aT);   // a^512
    float2 E[NC2];
#pragma unroll
    for (int c = 0; c < NC2; c++) E[c] = g_E[(b * NC2 + c) * PD + p];
    float2 S = make_float2(0.f, 0.f);
#pragma unroll
    for (int c = 0; c < NC2; c++) {
        g_carry[(b * NC2 + c) * PD + p] = S;
        S = make_float2(aT.x * S.x - aT.y * S.y + E[c].x,
                        aT.x * S.y + aT.y * S.x + E[c].y);
    }
}

// ---------------------------------------------------------------------------
// K3: [Cre|-Cim|D](128x640) @ [x_re;x_im;u](640 x L) + GELU. grid (L/128, BSZ).
// Chunks 0-7: pure fp16 copy staging from x planes. Chunks 8-9: fp32 u -> fp16.
// ---------------------------------------------------------------------------
__global__ void __launch_bounds__(256) k3_out(const float* __restrict__ u,
                                              float* __restrict__ out)
{
    __shared__ __align__(16) __half sh[64][SROW];

    const int b = blockIdx.y, lbase = blockIdx.x * 128;
    const int tid = threadIdx.x, lane = tid & 31, wid = tid >> 5;
    const int wm = wid >> 1, wn = wid & 1;
    const unsigned s_base = smem_u32(&sh[0][0]);
    const int row = tid >> 2, quarter = tid & 3;

    float c[2][8][4];
#pragma unroll
    for (int mi = 0; mi < 2; mi++)
#pragma unroll
        for (int ni = 0; ni < 8; ni++)
#pragma unroll
            for (int q = 0; q < 4; q++) c[mi][ni][q] = 0.f;

    uint4 pv[8];

    auto prefetch = [&](int cc) {
        if (cc < 8) {
            const __half* src = (cc >= 4) ? g_xi : g_xr;
            const uint4* s = (const uint4*)(src +
                ((size_t)b * PD + (cc & 3) * 64 + row) * LSEQ + lbase + quarter * 32);
#pragma unroll
            for (int q = 0; q < 4; q++) pv[q] = s[q];
        } else {
            const uint4* s = (const uint4*)(u +
                ((size_t)b * HD + (cc - 8) * 64 + row) * LSEQ + lbase + quarter * 32);
#pragma unroll
            for (int q = 0; q < 8; q++) pv[q] = s[q];
        }
    };
    auto stage = [&](int cc) {
        if (cc < 8) {
#pragma unroll
            for (int q = 0; q < 4; q++)
                *(uint4*)&sh[row][quarter * 32 + q * 8] = pv[q];
        } else {
#pragma unroll
            for (int q = 0; q < 4; q++) {
                float4 v0 = *(float4*)&pv[2 * q];
                float4 v1 = *(float4*)&pv[2 * q + 1];
                uint4 pk;
                pk.x = pack_f16(v0.x, v0.y); pk.y = pack_f16(v0.z, v0.w);
                pk.z = pack_f16(v1.x, v1.y); pk.w = pack_f16(v1.z, v1.w);
                *(uint4*)&sh[row][quarter * 32 + q * 8] = pk;
            }
        }
    };

    prefetch(0);
    const int blk0 = wm * 2;
#pragma unroll 1
    for (int cc = 0; cc < 10; cc++) {
        stage(cc);
        __syncthreads();
        if (cc < 9) prefetch(cc + 1);
        mma_block<4, true>(c, g_WcPk, 40, blk0, blk0 + 1, cc * 4, s_base, lane, wn);
        __syncthreads();
    }

#pragma unroll
    for (int mi = 0; mi < 2; mi++) {
#pragma unroll
        for (int ni = 0; ni < 8; ni++) {
            int r0  = wm * 32 + mi * 16 + (lane >> 2);
            int col = lbase + wn * 64 + ni * 8 + (lane & 3) * 2;
            float y0 = c[mi][ni][0], y1 = c[mi][ni][1];
            float y2 = c[mi][ni][2], y3 = c[mi][ni][3];
            y0 = 0.5f * y0 * (1.f + erff(y0 * 0.70710678118654752f));
            y1 = 0.5f * y1 * (1.f + erff(y1 * 0.70710678118654752f));
            y2 = 0.5f * y2 * (1.f + erff(y2 * 0.70710678118654752f));
            y3 = 0.5f * y3 * (1.f + erff(y3 * 0.70710678118654752f));
            *(float2*)&out[((size_t)b * HD + r0) * LSEQ + col]     = make_float2(y0, y1);
            *(float2*)&out[((size_t)b * HD + r0 + 8) * LSEQ + col] = make_float2(y2, y3);
        }
    }
}

// ---------------------------------------------------------------------------
extern "C" void kernel_launch(void* const* d_in, const int* in_sizes, int n_in,
                              void* d_out, int out_size)
{
    (void)in_sizes; (void)n_in; (void)out_size;
    const float* u   = (const float*)d_in[0];
    const float* Are = (const float*)d_in[1];
    const float* Aim = (const float*)d_in[2];
    const float* Bre = (const float*)d_in[3];
    const float* Bim = (const float*)d_in[4];
    const float* Cre = (const float*)d_in[5];
    const float* Cim = (const float*)d_in[6];
    const float* Dm  = (const float*)d_in[7];
    float* out = (float*)d_out;

    k0_prep    <<<80, 256>>>(Bre, Bim, Cre, Cim, Dm);
    k1_bu      <<<dim3(LSEQ / 128, 1, BSZ), 256>>>(u);
    k2a_local  <<<dim3(NC2, PD / 8, BSZ), 256>>>(Are, Aim);
    k2b_carry  <<<BSZ, 256>>>(Are, Aim);
    k2c_replay <<<dim3(NC2, PD / 8, BSZ), 256>>>(Are, Aim);
    k3_out     <<<dim3(LSEQ / 128, BSZ), 256>>>(u, out);
}